// round 1
// baseline (speedup 1.0000x reference)
#include <cuda_runtime.h>
#include <cstdint>

// Problem shapes (fixed by setup_inputs)
#define C_      500
#define G_      200
#define F_      500
#define NCLUST_ 10
#define NFRAG_  5000000
#define CGF_    (C_ * G_ * F_)        // 50,000,000 bins
#define CNT_WORDS_ (CGF_ / 4)         // 12,500,000 u32 words (byte-packed counts)

// Scratch (device globals — no allocation allowed in kernel_launch)
__device__ unsigned int g_cnt[CNT_WORDS_];   // 50 MB byte-packed histogram
__device__ float2       g_b2[G_ * F_];       // {bincounts[g,f], baseline[genes_oi[g],f]}
__device__ float2       g_dc[C_];            // {dw[labels[c]], cm[labels[c]]}
__device__ float        g_S[NCLUST_ * G_];   // sum_f exp(u) per (cluster, gene)

// ---------------------------------------------------------------------------
// 1) Zero the byte-packed count array (uint4 stores, 50 MB)
__global__ void k_zero_cnt() {
    unsigned i = blockIdx.x * blockDim.x + threadIdx.x;
    if (i < CNT_WORDS_ / 4)
        reinterpret_cast<uint4*>(g_cnt)[i] = make_uint4(0u, 0u, 0u, 0u);
}

// ---------------------------------------------------------------------------
// 2) Build fused gather tables + zero output (C*G == G*F == 100000)
__global__ void k_prep(const float* __restrict__ bincounts,
                       const float* __restrict__ baseline,
                       const float* __restrict__ dw,
                       const float* __restrict__ cm,
                       const int*   __restrict__ genes_oi,
                       const int*   __restrict__ labels,
                       float*       __restrict__ out) {
    int i = blockIdx.x * blockDim.x + threadIdx.x;
    if (i < G_ * F_) {
        int g = i / F_;
        int f = i - g * F_;
        g_b2[i] = make_float2(bincounts[i], baseline[genes_oi[g] * F_ + f]);
        out[i]  = 0.0f;                     // C_*G_ == G_*F_ == 100000
    }
    if (i < C_) {
        int k = labels[i];
        g_dc[i] = make_float2(dw[k], cm[k]);
    }
}

// ---------------------------------------------------------------------------
// 3) S[k,g] = sum_f exp(bincounts[g,f]*dw[k] + baseline_g[g,f] + cm[k])
//    One warp per (k,g) pair: 2000 warps total.
__global__ void k_expsum(const float* __restrict__ dw,
                         const float* __restrict__ cm) {
    int warp = (blockIdx.x * blockDim.x + threadIdx.x) >> 5;
    int lane = threadIdx.x & 31;
    if (warp >= NCLUST_ * G_) return;
    int k = warp / G_;
    int g = warp - k * G_;
    float a = dw[k];
    float b = cm[k];
    float s = 0.0f;
    #pragma unroll 4
    for (int f = lane; f < F_; f += 32) {
        float2 t = g_b2[g * F_ + f];
        s += __expf(fmaf(t.x, a, t.y + b));
    }
    #pragma unroll
    for (int o = 16; o; o >>= 1) s += __shfl_xor_sync(0xffffffffu, s, o);
    if (lane == 0) g_S[warp] = s;
}

// ---------------------------------------------------------------------------
// 4) Fragment pass: for each fragment add u, subtract log(old_count+1)
//    (incremental lgamma: sum over insertions of log(n+1) == log(count!))
__global__ void k_frag(const int* __restrict__ cgix,
                       const int* __restrict__ binix,
                       float*     __restrict__ out) {
    unsigned i = blockIdx.x * blockDim.x + threadIdx.x;
    if (i >= NFRAG_ / 4) return;
    int4 cg4 = reinterpret_cast<const int4*>(cgix)[i];
    int4 f4  = reinterpret_cast<const int4*>(binix)[i];
    unsigned cgs[4] = {(unsigned)cg4.x, (unsigned)cg4.y, (unsigned)cg4.z, (unsigned)cg4.w};
    unsigned fs[4]  = {(unsigned)f4.x,  (unsigned)f4.y,  (unsigned)f4.z,  (unsigned)f4.w};
    #pragma unroll
    for (int j = 0; j < 4; j++) {
        unsigned cg = cgs[j];
        unsigned f  = fs[j];
        unsigned c  = cg / G_;                 // const divisor -> mul/shift
        unsigned g  = cg - c * G_;
        float2 dc = g_dc[c];                   // 4 KB, L1-resident
        float2 bb = g_b2[g * F_ + f];          // 800 KB, L2-resident
        float u = fmaf(bb.x, dc.x, bb.y + dc.y);

        unsigned bin = cg * (unsigned)F_ + f;  // < 50M
        unsigned sh  = (bin & 3u) * 8u;
        unsigned old = atomicAdd(&g_cnt[bin >> 2], 1u << sh);
        unsigned oc  = (old >> sh) & 0xFFu;    // pre-increment byte count

        float val = u;
        if (oc) val -= __logf((float)(oc + 1u));
        atomicAdd(&out[cg], val);              // no return use -> RED
    }
}

// ---------------------------------------------------------------------------
// 5) Epilogue: out[c,g] -= S[labels[c], g]
__global__ void k_epi(const int* __restrict__ labels,
                      float*     __restrict__ out) {
    int i = blockIdx.x * blockDim.x + threadIdx.x;
    if (i >= C_ * G_) return;
    int c = i / G_;
    int g = i - c * G_;
    out[i] -= g_S[labels[c] * G_ + g];
}

// ---------------------------------------------------------------------------
extern "C" void kernel_launch(void* const* d_in, const int* in_sizes, int n_in,
                              void* d_out, int out_size) {
    const float* bincounts = (const float*)d_in[0];   // (G,F)
    const float* baseline  = (const float*)d_in[1];   // (N_GENES,F)
    const float* dw        = (const float*)d_in[2];   // (N_CLUST,1,1)
    const float* cm        = (const float*)d_in[3];   // (N_CLUST,)
    const int*   genes_oi  = (const int*)d_in[4];     // (G,)
    const int*   labels    = (const int*)d_in[5];     // (C,)
    const int*   cgix      = (const int*)d_in[6];     // (NFRAG,)
    const int*   binix     = (const int*)d_in[7];     // (NFRAG,)
    float*       out       = (float*)d_out;           // (C,G)

    (void)in_sizes; (void)n_in; (void)out_size;

    // 1) zero 50 MB histogram
    {
        int n = CNT_WORDS_ / 4;
        k_zero_cnt<<<(n + 255) / 256, 256>>>();
    }
    // 2) fused tables + zero out
    {
        int n = G_ * F_;
        k_prep<<<(n + 255) / 256, 256>>>(bincounts, baseline, dw, cm,
                                         genes_oi, labels, out);
    }
    // 3) per-(cluster,gene) exp sums: 2000 warps
    {
        int nthreads = NCLUST_ * G_ * 32;
        k_expsum<<<(nthreads + 255) / 256, 256>>>(dw, cm);
    }
    // 4) fragment pass (4 fragments per thread via int4 loads)
    {
        int n = NFRAG_ / 4;
        k_frag<<<(n + 255) / 256, 256>>>(cgix, binix, out);
    }
    // 5) epilogue
    {
        int n = C_ * G_;
        k_epi<<<(n + 255) / 256, 256>>>(labels, out);
    }
}

// round 2
// speedup vs baseline: 1.5340x; 1.5340x over previous
#include <cuda_runtime.h>
#include <cstdint>

// Problem shapes (fixed by setup_inputs)
#define C_      500
#define G_      200
#define F_      500
#define NCLUST_ 10
#define NFRAG_  5000000
#define GF_     (G_ * F_)             // 100,000
#define CGF_    (C_ * G_ * F_)        // 50,000,000 bins
#define CNT_WORDS_ (CGF_ / 4)         // 12,500,000 u32 (byte-packed counts)

// Scratch (device globals — no allocation allowed)
__device__ unsigned int g_cnt[CNT_WORDS_];            // 50 MB byte-packed histogram
__device__ __align__(16) float g_u[NCLUST_ * GF_];    // 4 MB: u[k][g*F+f]
__device__ float g_S[NCLUST_ * G_];                   // sum_f exp(u) per (k,g)

// ---------------------------------------------------------------------------
// 1) Zero the byte-packed count array (uint4 stores, 50 MB)
__global__ void k_zero_cnt() {
    unsigned i = blockIdx.x * blockDim.x + threadIdx.x;
    if (i < CNT_WORDS_ / 4)
        reinterpret_cast<uint4*>(g_cnt)[i] = make_uint4(0u, 0u, 0u, 0u);
}

// ---------------------------------------------------------------------------
// 2) u_tab[k][g,f] = bincounts[g,f]*dw[k] + baseline[genes_oi[g],f] + cm[k]
__global__ void k_utab(const float* __restrict__ bincounts,
                       const float* __restrict__ baseline,
                       const float* __restrict__ dw,
                       const float* __restrict__ cm,
                       const int*   __restrict__ genes_oi) {
    int i = blockIdx.x * blockDim.x + threadIdx.x;
    if (i >= NCLUST_ * GF_) return;
    int k  = i / GF_;
    int gf = i - k * GF_;
    int g  = gf / F_;
    int f  = gf - g * F_;
    g_u[i] = fmaf(bincounts[gf], dw[k], baseline[genes_oi[g] * F_ + f] + cm[k]);
}

// ---------------------------------------------------------------------------
// 3) S[k,g] = sum_f exp(u[k][g,f]) ; one warp per (k,g) — fully coalesced
__global__ void k_expsum() {
    int warp = (blockIdx.x * blockDim.x + threadIdx.x) >> 5;
    int lane = threadIdx.x & 31;
    if (warp >= NCLUST_ * G_) return;
    const float* u = g_u + (size_t)warp * F_;   // k*GF + g*F == warp*F
    float s = 0.0f;
    #pragma unroll 4
    for (int f = lane; f < F_; f += 32) s += __expf(u[f]);
    #pragma unroll
    for (int o = 16; o; o >>= 1) s += __shfl_xor_sync(0xffffffffu, s, o);
    if (lane == 0) g_S[warp] = s;
}

// ---------------------------------------------------------------------------
// 4) Fragment pass: ONLY a no-return byte-packed RED per fragment
__global__ void k_frag(const int* __restrict__ cgix,
                       const int* __restrict__ binix) {
    unsigned i = blockIdx.x * blockDim.x + threadIdx.x;
    if (i >= NFRAG_ / 4) return;
    int4 cg4 = reinterpret_cast<const int4*>(cgix)[i];
    int4 f4  = reinterpret_cast<const int4*>(binix)[i];
    unsigned b0 = (unsigned)cg4.x * F_ + (unsigned)f4.x;
    unsigned b1 = (unsigned)cg4.y * F_ + (unsigned)f4.y;
    unsigned b2 = (unsigned)cg4.z * F_ + (unsigned)f4.z;
    unsigned b3 = (unsigned)cg4.w * F_ + (unsigned)f4.w;
    atomicAdd(&g_cnt[b0 >> 2], 1u << ((b0 & 3u) * 8u));
    atomicAdd(&g_cnt[b1 >> 2], 1u << ((b1 & 3u) * 8u));
    atomicAdd(&g_cnt[b2 >> 2], 1u << ((b2 & 3u) * 8u));
    atomicAdd(&g_cnt[b3 >> 2], 1u << ((b3 & 3u) * 8u));
}

// ---------------------------------------------------------------------------
// 5) Bin sweep: one warp per cg. Coalesced count read, sparse coalesced u read.
//    out[cg] = sum_{f: n>0} (n*u - log(n!)) - S[k,g]
__global__ void k_out(const int* __restrict__ labels,
                      float*     __restrict__ out) {
    __shared__ float s_lf[32];                 // s_lf[n] = log(n!)
    if (threadIdx.x < 32) s_lf[threadIdx.x] = lgammaf((float)threadIdx.x + 1.0f);
    __syncthreads();

    int warp = (blockIdx.x * blockDim.x + threadIdx.x) >> 5;
    int lane = threadIdx.x & 31;
    if (warp >= C_ * G_) return;
    int cg = warp;
    int c  = cg / G_;
    int g  = cg - c * G_;
    int k  = labels[c];

    const unsigned* cnt = g_cnt + (size_t)cg * (F_ / 4);          // 125 words
    const float*    ut  = g_u + (size_t)k * GF_ + (size_t)g * F_; // 500 floats, 16B-aligned

    float acc = 0.0f;
    #pragma unroll
    for (int it = 0; it < 4; it++) {
        int w = it * 32 + lane;
        if (w < F_ / 4) {
            unsigned cw = cnt[w];
            if (cw) {
                float4 u4 = *reinterpret_cast<const float4*>(ut + w * 4);
                unsigned n0 =  cw        & 255u;
                unsigned n1 = (cw >> 8)  & 255u;
                unsigned n2 = (cw >> 16) & 255u;
                unsigned n3 =  cw >> 24;
                if (n0) acc += fmaf((float)n0, u4.x, -s_lf[n0]);
                if (n1) acc += fmaf((float)n1, u4.y, -s_lf[n1]);
                if (n2) acc += fmaf((float)n2, u4.z, -s_lf[n2]);
                if (n3) acc += fmaf((float)n3, u4.w, -s_lf[n3]);
            }
        }
    }
    #pragma unroll
    for (int o = 16; o; o >>= 1) acc += __shfl_xor_sync(0xffffffffu, acc, o);
    if (lane == 0) out[cg] = acc - g_S[k * G_ + g];
}

// ---------------------------------------------------------------------------
extern "C" void kernel_launch(void* const* d_in, const int* in_sizes, int n_in,
                              void* d_out, int out_size) {
    const float* bincounts = (const float*)d_in[0];   // (G,F)
    const float* baseline  = (const float*)d_in[1];   // (N_GENES,F)
    const float* dw        = (const float*)d_in[2];   // (N_CLUST,1,1)
    const float* cm        = (const float*)d_in[3];   // (N_CLUST,)
    const int*   genes_oi  = (const int*)d_in[4];     // (G,)
    const int*   labels    = (const int*)d_in[5];     // (C,)
    const int*   cgix      = (const int*)d_in[6];     // (NFRAG,)
    const int*   binix     = (const int*)d_in[7];     // (NFRAG,)
    float*       out       = (float*)d_out;           // (C,G)

    (void)in_sizes; (void)n_in; (void)out_size;

    // 1) zero 50 MB histogram
    {
        int n = CNT_WORDS_ / 4;
        k_zero_cnt<<<(n + 255) / 256, 256>>>();
    }
    // 2) 4 MB u table
    {
        int n = NCLUST_ * GF_;
        k_utab<<<(n + 255) / 256, 256>>>(bincounts, baseline, dw, cm, genes_oi);
    }
    // 3) exp sums (2000 warps)
    {
        int nthreads = NCLUST_ * G_ * 32;
        k_expsum<<<(nthreads + 255) / 256, 256>>>();
    }
    // 4) fragment histogram (pure RED)
    {
        int n = NFRAG_ / 4;
        k_frag<<<(n + 255) / 256, 256>>>(cgix, binix);
    }
    // 5) bin sweep -> out
    {
        long long nthreads = (long long)C_ * G_ * 32;
        k_out<<<(int)((nthreads + 255) / 256), 256>>>(labels, out);
    }
}